// round 3
// baseline (speedup 1.0000x reference)
#include <cuda_runtime.h>
#include <math.h>

#define Nn 128
#define C  2048
#define L  512
#define TT 512
#define TSTRIDE 2052
#define SMEM_FLOATS (8*TSTRIDE + 16 + 8 + 2)
#define SMEM_BYTES  (SMEM_FLOATS*4)

// -------- scratch (device globals; no allocations allowed) --------
__device__ float g_theta[Nn*L];
__device__ float g_u[Nn*C];
__device__ float g_v[Nn*C];
__device__ float g_lat[Nn*L];
__device__ float g_pre[Nn*C];
__device__ float g_part[4*Nn*C];   // split-K partials (max 4*128*2048 floats)

// ============ skinny projection: part[s][n][o] = sum_{k in chunk s} act[n,k]*W(o,k) ============
// WT=false: w is [O][K] row-major. WT=true: w is [K][O] row-major.
template<bool WT>
__global__ __launch_bounds__(256) void proj_kernel(
    const float* __restrict__ act, const float* __restrict__ w,
    float* __restrict__ part, int K, int O, int kchunk)
{
    __shared__ float th[Nn*68];    // [n][kk], stride 68
    __shared__ float ws[64*33];    // [kk][oc], stride 33
    const int tid = threadIdx.x;
    const int ocbase = blockIdx.x * 32;
    const int sidx = blockIdx.y;
    const int k0 = sidx * kchunk;
    const int oc = tid & 31;
    const int ng = tid >> 5;       // 8 groups of 16 n each
    float acc[16];
#pragma unroll
    for (int i = 0; i < 16; i++) acc[i] = 0.f;

    for (int kb = k0; kb < k0 + kchunk; kb += 64) {
        // stage act[0:128][kb:kb+64]
#pragma unroll
        for (int j = 0; j < 8; j++) {
            int f = tid + 256*j;
            int n = f >> 4;
            int kq = (f & 15) << 2;
            float4 v4 = *(const float4*)(act + (size_t)n*K + kb + kq);
            *(float4*)(th + n*68 + kq) = v4;
        }
        if (WT) {
#pragma unroll
            for (int j = 0; j < 2; j++) {
                int f = tid + 256*j;
                int kk = f >> 3;
                int oq = (f & 7) << 2;
                float4 v4 = *(const float4*)(w + (size_t)(kb+kk)*O + ocbase + oq);
                ws[kk*33 + oq + 0] = v4.x;
                ws[kk*33 + oq + 1] = v4.y;
                ws[kk*33 + oq + 2] = v4.z;
                ws[kk*33 + oq + 3] = v4.w;
            }
        } else {
#pragma unroll
            for (int j = 0; j < 2; j++) {
                int f = tid + 256*j;
                int o = f >> 4;
                int kq = (f & 15) << 2;
                float4 v4 = *(const float4*)(w + (size_t)(ocbase+o)*K + kb + kq);
                ws[(kq+0)*33 + o] = v4.x;
                ws[(kq+1)*33 + o] = v4.y;
                ws[(kq+2)*33 + o] = v4.z;
                ws[(kq+3)*33 + o] = v4.w;
            }
        }
        __syncthreads();
        const float* tp = th + ng*16*68;
#pragma unroll 4
        for (int kk = 0; kk < 64; kk++) {
            float wv = ws[kk*33 + oc];
#pragma unroll
            for (int i = 0; i < 16; i++)
                acc[i] += tp[i*68 + kk] * wv;   // broadcast smem reads
        }
        __syncthreads();
    }
    float* dst = part + (size_t)(sidx*Nn + ng*16)*O + ocbase + oc;
#pragma unroll
    for (int i = 0; i < 16; i++)
        dst[(size_t)i*O] = acc[i];
}

// ============ deterministic split-K reduce + bias (O is a power of two) ============
__global__ __launch_bounds__(256) void reduce_kernel(
    const float* __restrict__ part, float* __restrict__ dst,
    const float* __restrict__ bias, int S, int omask, int total)
{
    int i = blockIdx.x*blockDim.x + threadIdx.x;
    if (i >= total) return;
    float a = 0.f;
    for (int s = 0; s < S; s++) a += part[(size_t)s*total + i];
    if (bias) a += bias[i & omask];
    dst[i] = a;
}

// ============ single-pass flash attention over t (S_q == 1), v[n,c] = lt p ============
__global__ __launch_bounds__(512) void attn_kernel(
    const float* __restrict__ lt, const float* __restrict__ u, float* __restrict__ v)
{
    extern __shared__ float sm[];
    float* tile = sm;                  // [8][TSTRIDE] transposed chunk (t-major)
    float* sp   = sm + 8*TSTRIDE;      // 16 warp partial scores
    float* wsh  = sp + 16;             // 8 chunk exp-weights
    float* csh  = wsh + 8;             // [0]=corr, [1]=final denom

    const int n = blockIdx.x;
    const int tid = threadIdx.x;
    const int lane = tid & 31, wid = tid >> 5;
    const float* ltn = lt + (size_t)n * C * TT;

    // warp (wid) owns score row t = wid>>1 and channel half (wid&1); cache u slice in regs
    const int trow = wid >> 1;
    const int chalf = (wid & 1) * 1024;
    float ureg[32];
#pragma unroll
    for (int k = 0; k < 32; k++) ureg[k] = u[n*C + chalf + k*32 + lane];

    float4 vacc = make_float4(0.f, 0.f, 0.f, 0.f);
    float m_run = -1e30f, s_run = 0.f;

    float4 stg[8];
    // prologue: load + transpose-store chunk 0
#pragma unroll
    for (int j = 0; j < 8; j++) {
        int q = tid + 512*j; int c = q >> 1; int toff = (q & 1) << 2;
        stg[j] = *(const float4*)(ltn + (size_t)c*TT + toff);
    }
#pragma unroll
    for (int j = 0; j < 8; j++) {
        int q = tid + 512*j; int c = q >> 1; int tr = (q & 1) << 2;
        tile[(tr+0)*TSTRIDE + c] = stg[j].x;
        tile[(tr+1)*TSTRIDE + c] = stg[j].y;
        tile[(tr+2)*TSTRIDE + c] = stg[j].z;
        tile[(tr+3)*TSTRIDE + c] = stg[j].w;
    }

    for (int ch = 0; ch < 64; ch++) {
        // prefetch next chunk into registers (8 LDG.128 in flight per thread)
        if (ch + 1 < 64) {
            int t0 = (ch + 1) * 8;
#pragma unroll
            for (int j = 0; j < 8; j++) {
                int q = tid + 512*j; int c = q >> 1; int toff = (q & 1) << 2;
                stg[j] = *(const float4*)(ltn + (size_t)c*TT + t0 + toff);
            }
        }
        __syncthreads();   // tile[ch] visible

        // ---- scores: warp reduces its 1024-channel half of row trow ----
        float a0=0.f, a1=0.f, a2=0.f, a3=0.f;
        const float* tr_ = tile + trow*TSTRIDE + chalf + lane;
#pragma unroll
        for (int k = 0; k < 32; k += 4) {
            a0 += ureg[k+0] * tr_[(k+0)*32];
            a1 += ureg[k+1] * tr_[(k+1)*32];
            a2 += ureg[k+2] * tr_[(k+2)*32];
            a3 += ureg[k+3] * tr_[(k+3)*32];
        }
        float a = (a0 + a1) + (a2 + a3);
#pragma unroll
        for (int off = 16; off; off >>= 1) a += __shfl_xor_sync(~0u, a, off);
        if (lane == 0) sp[wid] = a;
        __syncthreads();

        // ---- online softmax update (warp 0, lanes 0..7 = 8 t values) ----
        if (wid == 0 && lane < 8) {
            float sc = (sp[2*lane] + sp[2*lane+1]) * 0.044194173824159216f; // 1/sqrt(512)
            float mc = sc;
#pragma unroll
            for (int off = 4; off; off >>= 1) mc = fmaxf(mc, __shfl_xor_sync(0xFFu, mc, off));
            float m_new = fmaxf(m_run, mc);
            float corr  = __expf(m_run - m_new);
            float wv    = __expf(sc - m_new);
            float ssum  = wv;
#pragma unroll
            for (int off = 4; off; off >>= 1) ssum += __shfl_xor_sync(0xFFu, ssum, off);
            s_run = s_run * corr + ssum;
            m_run = m_new;
            wsh[lane] = wv;
            if (lane == 0) csh[0] = corr;
            if (ch == 63 && lane == 0) csh[1] = s_run;
        }
        __syncthreads();

        // ---- v accumulation: thread owns channels 4*tid..4*tid+3 ----
        float corr = csh[0];
        vacc.x *= corr; vacc.y *= corr; vacc.z *= corr; vacc.w *= corr;
        const float4* t4 = (const float4*)tile;
#pragma unroll
        for (int t = 0; t < 8; t++) {
            float wt = wsh[t];
            float4 x = t4[t*(TSTRIDE/4) + tid];
            vacc.x += wt*x.x; vacc.y += wt*x.y; vacc.z += wt*x.z; vacc.w += wt*x.w;
        }
        __syncthreads();   // tile consumed

        // transpose-store prefetched chunk
        if (ch + 1 < 64) {
#pragma unroll
            for (int j = 0; j < 8; j++) {
                int q = tid + 512*j; int c = q >> 1; int tr = (q & 1) << 2;
                tile[(tr+0)*TSTRIDE + c] = stg[j].x;
                tile[(tr+1)*TSTRIDE + c] = stg[j].y;
                tile[(tr+2)*TSTRIDE + c] = stg[j].z;
                tile[(tr+3)*TSTRIDE + c] = stg[j].w;
            }
        }
    }

    float inv = 1.0f / csh[1];
    *(float4*)(v + (size_t)n*C + tid*4) =
        make_float4(vacc.x*inv, vacc.y*inv, vacc.z*inv, vacc.w*inv);
}

// ============ LayerNorm over channels ============
__global__ __launch_bounds__(256) void ln_kernel(
    const float* __restrict__ pre, const float* __restrict__ lnw,
    const float* __restrict__ lnb, float* __restrict__ out)
{
    __shared__ float rs[8], rss[8], bc[2];
    const int n = blockIdx.x, tid = threadIdx.x;
    const int lane = tid & 31, wid = tid >> 5;
    const float* row = pre + (size_t)n*C;
    float x[8];
    float s = 0.f, ss = 0.f;
#pragma unroll
    for (int j = 0; j < 2; j++) {
        float4 v4 = *(const float4*)(row + j*1024 + tid*4);
        x[j*4+0]=v4.x; x[j*4+1]=v4.y; x[j*4+2]=v4.z; x[j*4+3]=v4.w;
        s  += v4.x + v4.y + v4.z + v4.w;
        ss += v4.x*v4.x + v4.y*v4.y + v4.z*v4.z + v4.w*v4.w;
    }
#pragma unroll
    for (int off = 16; off; off >>= 1) {
        s  += __shfl_xor_sync(~0u, s,  off);
        ss += __shfl_xor_sync(~0u, ss, off);
    }
    if (lane == 0) { rs[wid] = s; rss[wid] = ss; }
    __syncthreads();
    if (tid == 0) {
        float S1 = 0.f, S2 = 0.f;
#pragma unroll
        for (int i = 0; i < 8; i++) { S1 += rs[i]; S2 += rss[i]; }
        float mu = S1 * (1.0f/C);
        float var = S2 * (1.0f/C) - mu*mu;
        bc[0] = mu;
        bc[1] = rsqrtf(var + 1e-5f);
    }
    __syncthreads();
    float mu = bc[0], rstd = bc[1];
#pragma unroll
    for (int j = 0; j < 2; j++) {
        int cbase = j*1024 + tid*4;
        float4 w4 = *(const float4*)(lnw + cbase);
        float4 b4 = *(const float4*)(lnb + cbase);
        float4 o;
        o.x = (x[j*4+0]-mu)*rstd*w4.x + b4.x;
        o.y = (x[j*4+1]-mu)*rstd*w4.y + b4.y;
        o.z = (x[j*4+2]-mu)*rstd*w4.z + b4.z;
        o.w = (x[j*4+3]-mu)*rstd*w4.w + b4.w;
        *(float4*)(out + (size_t)n*C + cbase) = o;
    }
}

extern "C" void kernel_launch(void* const* d_in, const int* in_sizes, int n_in,
                              void* d_out, int out_size)
{
    const float* st_feat = (const float*)d_in[0];
    const float* lt_feat = (const float*)d_in[1];
    const float* w_st    = (const float*)d_in[2];
    const float* b_st    = (const float*)d_in[3];
    const float* w_lt    = (const float*)d_in[4];
    const float* b_lt    = (const float*)d_in[5];  (void)b_lt; // softmax-invariant
    const float* w_g     = (const float*)d_in[6];
    const float* b_g     = (const float*)d_in[7];
    const float* w_out   = (const float*)d_in[8];
    const float* b_out   = (const float*)d_in[9];
    const float* ln_w    = (const float*)d_in[10];
    const float* ln_b    = (const float*)d_in[11];
    float* out = (float*)d_out;

    float *theta, *u, *v, *lat, *pre, *part;
    cudaGetSymbolAddress((void**)&theta, g_theta);
    cudaGetSymbolAddress((void**)&u,     g_u);
    cudaGetSymbolAddress((void**)&v,     g_v);
    cudaGetSymbolAddress((void**)&lat,   g_lat);
    cudaGetSymbolAddress((void**)&pre,   g_pre);
    cudaGetSymbolAddress((void**)&part,  g_part);

    cudaFuncSetAttribute(attn_kernel,
        cudaFuncAttributeMaxDynamicSharedMemorySize, SMEM_BYTES);

    // 1. theta[n,l] = st_feat @ w_st^T + b_st        [128,512]
    proj_kernel<false><<<dim3(L/32, 8), 256>>>(st_feat, w_st, part, C, L, C/8);
    reduce_kernel<<<(Nn*L+255)/256, 256>>>(part, theta, b_st, 8, L-1, Nn*L);

    // 2. u[n,c] = theta @ w_lt (w_lt is [L][C] -> transposed use)  [128,2048]
    proj_kernel<true><<<dim3(C/32, 4), 256>>>(theta, w_lt, part, L, C, L/4);
    reduce_kernel<<<(Nn*C+255)/256, 256>>>(part, u, (const float*)0, 4, C-1, Nn*C);

    // 3. v[n,c] = lt @ softmax(u.lt / sqrt(L))       [128,2048]
    attn_kernel<<<Nn, 512, SMEM_BYTES>>>(lt_feat, u, v);

    // 4. lat[n,l] = v @ w_g^T + b_g                  [128,512]
    proj_kernel<false><<<dim3(L/32, 8), 256>>>(v, w_g, part, C, L, C/8);
    reduce_kernel<<<(Nn*L+255)/256, 256>>>(part, lat, b_g, 8, L-1, Nn*L);

    // 5. pre[n,c] = lat @ w_out^T + b_out            [128,2048]
    proj_kernel<false><<<dim3(C/32, 4), 256>>>(lat, w_out, part, L, C, L/4);
    reduce_kernel<<<(Nn*C+255)/256, 256>>>(part, pre, b_out, 4, C-1, Nn*C);

    // 6. LayerNorm -> out
    ln_kernel<<<Nn, 256>>>(pre, ln_w, ln_b, out);
}